// round 8
// baseline (speedup 1.0000x reference)
#include <cuda_runtime.h>
#include <cuda_bf16.h>
#include <math.h>
#include <stdint.h>

// Problem constants (fixed shapes)
#define T_TOK   16384
#define DMODEL  512
#define HDIM    1024
#define NEXP    8
#define NDISP   (T_TOK * 2)              // T * top_k
#define PAD_CAP (NDISP + NEXP * 128)     // per-expert padding to 128-row tiles
#define MAXTILES ((NDISP / 128) + NEXP)  // 264

// ---------------- scratch (device globals; no allocations) ----------------
__device__ float g_h[(size_t)PAD_CAP * HDIM];   // GEMM1 output (post-GELU)
__device__ float g_y[(size_t)PAD_CAP * DMODEL]; // GEMM2 output (pre-scaled)
__device__ float g_zero[DMODEL];                // zero row for padded gathers
__device__ int   g_row_disp[PAD_CAP];           // padded row -> dispatch idx (or -1)
__device__ float g_row_scale[PAD_CAP];          // gate score per padded row
__device__ int   g_dest_row[NDISP];             // dispatch idx -> padded row
__device__ int   g_expert_of[NDISP];
__device__ float g_scale_of[NDISP];
__device__ int   g_count[NEXP];
__device__ int   g_cursor[NEXP];
__device__ int   g_pad_off[NEXP];
__device__ int   g_tile_start[NEXP + 1];

// ---------------- packed f32x2 helpers ----------------
#define FMA2(acc, a2, b2)                                              \
    asm("fma.rn.f32x2 %0, %1, %2, %0;" : "+l"(acc) : "l"(a2), "l"(b2))

#define UNPACK2F(xf, yf, src)                                          \
    do {                                                               \
        uint32_t u0_, u1_;                                             \
        asm("mov.b64 {%0, %1}, %2;" : "=r"(u0_), "=r"(u1_) : "l"(src));\
        xf = __uint_as_float(u0_);                                     \
        yf = __uint_as_float(u1_);                                     \
    } while (0)

// ---------------- init ----------------
__global__ void init_kernel() {
    int i = blockIdx.x * blockDim.x + threadIdx.x;
    if (i < PAD_CAP) { g_row_disp[i] = -1; g_row_scale[i] = 0.f; }
    if (i < NEXP)    { g_count[i] = 0; g_cursor[i] = 0; }
}

// ---------------- gating: logits -> top2 -> softmax ----------------
__global__ void gate_kernel(const float* __restrict__ x,
                            const float* __restrict__ gw,
                            const float* __restrict__ gb) {
    int warp = threadIdx.x >> 5, lane = threadIdx.x & 31;
    int t = blockIdx.x * 8 + warp;
    if (t >= T_TOK) return;

    float acc[NEXP];
#pragma unroll
    for (int e = 0; e < NEXP; e++) acc[e] = 0.f;

    const float* xr = x + (size_t)t * DMODEL;
    for (int i = lane; i < DMODEL; i += 32) {
        float xv = xr[i];
        const float4* g4 = (const float4*)(gw + (size_t)i * NEXP);
        float4 a = g4[0], b = g4[1];
        acc[0] += xv * a.x; acc[1] += xv * a.y; acc[2] += xv * a.z; acc[3] += xv * a.w;
        acc[4] += xv * b.x; acc[5] += xv * b.y; acc[6] += xv * b.z; acc[7] += xv * b.w;
    }
#pragma unroll
    for (int e = 0; e < NEXP; e++) {
#pragma unroll
        for (int off = 16; off > 0; off >>= 1)
            acc[e] += __shfl_xor_sync(0xFFFFFFFFu, acc[e], off);
    }

    if (lane == 0) {
        float v0 = -1e30f, v1 = -1e30f; int i0 = 0, i1 = 0;
#pragma unroll
        for (int e = 0; e < NEXP; e++) {
            float v = acc[e] + gb[e];
            if (v > v0) { v1 = v0; i1 = i0; v0 = v; i0 = e; }
            else if (v > v1) { v1 = v; i1 = e; }
        }
        float ed = expf(v1 - v0);
        float inv = 1.f / (1.f + ed);
        g_expert_of[2 * t + 0] = i0; g_scale_of[2 * t + 0] = inv;
        g_expert_of[2 * t + 1] = i1; g_scale_of[2 * t + 1] = ed * inv;
        atomicAdd(&g_count[i0], 1);
        atomicAdd(&g_count[i1], 1);
    }
}

// ---------------- padded offsets ----------------
__global__ void offsets_kernel() {
    if (threadIdx.x == 0) {
        int off = 0, ts = 0;
        for (int e = 0; e < NEXP; e++) {
            g_pad_off[e] = off;
            g_tile_start[e] = ts;
            int tiles = (g_count[e] + 127) >> 7;
            ts += tiles;
            off += tiles * 128;
        }
        g_tile_start[NEXP] = ts;
    }
}

// ---------------- scatter dispatches into padded rows ----------------
__global__ void scatter_kernel() {
    int j = blockIdx.x * blockDim.x + threadIdx.x;
    if (j >= NDISP) return;
    int e = g_expert_of[j];
    int pos = atomicAdd(&g_cursor[e], 1);
    int r = g_pad_off[e] + pos;
    g_row_disp[r] = j;
    g_row_scale[r] = g_scale_of[j];
    g_dest_row[j] = r;
}

__device__ __forceinline__ float gelu_exact(float v) {
    return 0.5f * v * (1.f + erff(v * 0.70710678118654752440f));
}

// ---------------- grouped GEMM: 128x128x8, FMA2, dup-A smem, 3-stage ring ----------------
// As: [3][8][256] floats — A rows pre-duplicated: As[kk][2r]=As[kk][2r+1]=A[r][kk]
// Bs: [3][8][128] floats — 16B chunks XOR-swizzled: phys = c ^ ((c>>3)&7)
template <int KDIM, int NLD, bool LAYER1>
__global__ __launch_bounds__(256, 2) void gemm_kernel(const float* __restrict__ X,
                                                      const float* __restrict__ W,
                                                      const float* __restrict__ Bv) {
    __shared__ __align__(16) float As[3][8][256];
    __shared__ __align__(16) float Bs[3][8][128];
    __shared__ const float* Aptr[128];

    int rt = blockIdx.y;
    if (rt >= g_tile_start[NEXP]) return;
    int e = 0;
    while (e < NEXP - 1 && g_tile_start[e + 1] <= rt) e++;
    int row_base = g_pad_off[e] + (rt - g_tile_start[e]) * 128;
    int n0 = blockIdx.x * 128;

    int tid = threadIdx.x;
    if (tid < 128) {
        if (LAYER1) {
            int j = g_row_disp[row_base + tid];
            Aptr[tid] = (j >= 0) ? (X + (size_t)(j >> 1) * KDIM) : g_zero;
        } else {
            Aptr[tid] = g_h + (size_t)(row_base + tid) * KDIM;
        }
    }
    __syncthreads();

    const float* Wb = W + (size_t)e * KDIM * NLD + n0;

    // loader indices
    const int arow = tid >> 1, ahalf = tid & 1;      // A: row, k-half(4)
    const int brow = tid >> 5, bchunk = tid & 31;    // B: kk row, 16B chunk
    const int bphys = bchunk ^ ((bchunk >> 3) & 7);
    const float* aSrc = Aptr[arow] + ahalf * 4;
    const float* bSrc = Wb + (size_t)brow * NLD + bchunk * 4;

    // compute indices
    const int tx = tid & 15, ty = tid >> 4;
    const int c0 = 2 * tx, c1 = 2 * tx + 1;
    const int p0 = c0 ^ ((c0 >> 3) & 7);   // phys chunk of cols 8tx..8tx+3
    const int p1 = c1 ^ ((c1 >> 3) & 7);   // phys chunk of cols 8tx+4..8tx+7

    uint64_t acc[8][4];
#pragma unroll
    for (int i = 0; i < 8; i++)
#pragma unroll
        for (int jp = 0; jp < 4; jp++) acc[i][jp] = 0ull;

    const int KT = KDIM / 8;

    float4 aReg, bReg;

#define STORE_STAGE(sbuf)                                                   \
    do {                                                                    \
        float2 d0_ = make_float2(aReg.x, aReg.x);                           \
        float2 d1_ = make_float2(aReg.y, aReg.y);                           \
        float2 d2_ = make_float2(aReg.z, aReg.z);                           \
        float2 d3_ = make_float2(aReg.w, aReg.w);                           \
        *(float2*)&As[sbuf][ahalf * 4 + 0][2 * arow] = d0_;                 \
        *(float2*)&As[sbuf][ahalf * 4 + 1][2 * arow] = d1_;                 \
        *(float2*)&As[sbuf][ahalf * 4 + 2][2 * arow] = d2_;                 \
        *(float2*)&As[sbuf][ahalf * 4 + 3][2 * arow] = d3_;                 \
        *(float4*)&Bs[sbuf][brow][bphys * 4] = bReg;                        \
    } while (0)

    // prologue: fill stage 0 and 1
    aReg = *(const float4*)(aSrc);
    bReg = *(const float4*)(bSrc);
    STORE_STAGE(0);
    if (KT > 1) {
        aReg = *(const float4*)(aSrc + 8);
        bReg = *(const float4*)(bSrc + (size_t)8 * NLD);
        STORE_STAGE(1);
    }
    __syncthreads();

    int buf = 0;
    for (int kt = 0; kt < KT; ++kt) {
        if (kt + 2 < KT) {
            aReg = *(const float4*)(aSrc + (kt + 2) * 8);
            bReg = *(const float4*)(bSrc + (size_t)(kt + 2) * 8 * NLD);
        }

#pragma unroll
        for (int kk = 0; kk < 8; ++kk) {
            // B pairs straight from shared (contiguous floats as u64 pairs)
            ulonglong2 bv0 = *(const ulonglong2*)&Bs[buf][kk][p0 * 4];
            ulonglong2 bv1 = *(const ulonglong2*)&Bs[buf][kk][p1 * 4];
            // A dup-pairs for rows ty*4..ty*4+3
            ulonglong2 av0 = *(const ulonglong2*)&As[buf][kk][8 * ty];
            ulonglong2 av1 = *(const ulonglong2*)&As[buf][kk][8 * ty + 4];
            FMA2(acc[0][0], av0.x, bv0.x); FMA2(acc[0][1], av0.x, bv0.y);
            FMA2(acc[0][2], av0.x, bv1.x); FMA2(acc[0][3], av0.x, bv1.y);
            FMA2(acc[1][0], av0.y, bv0.x); FMA2(acc[1][1], av0.y, bv0.y);
            FMA2(acc[1][2], av0.y, bv1.x); FMA2(acc[1][3], av0.y, bv1.y);
            FMA2(acc[2][0], av1.x, bv0.x); FMA2(acc[2][1], av1.x, bv0.y);
            FMA2(acc[2][2], av1.x, bv1.x); FMA2(acc[2][3], av1.x, bv1.y);
            FMA2(acc[3][0], av1.y, bv0.x); FMA2(acc[3][1], av1.y, bv0.y);
            FMA2(acc[3][2], av1.y, bv1.x); FMA2(acc[3][3], av1.y, bv1.y);
            // rows 64+ty*4..64+ty*4+3 (dup idx 128+8ty)
            ulonglong2 av2 = *(const ulonglong2*)&As[buf][kk][128 + 8 * ty];
            ulonglong2 av3 = *(const ulonglong2*)&As[buf][kk][128 + 8 * ty + 4];
            FMA2(acc[4][0], av2.x, bv0.x); FMA2(acc[4][1], av2.x, bv0.y);
            FMA2(acc[4][2], av2.x, bv1.x); FMA2(acc[4][3], av2.x, bv1.y);
            FMA2(acc[5][0], av2.y, bv0.x); FMA2(acc[5][1], av2.y, bv0.y);
            FMA2(acc[5][2], av2.y, bv1.x); FMA2(acc[5][3], av2.y, bv1.y);
            FMA2(acc[6][0], av3.x, bv0.x); FMA2(acc[6][1], av3.x, bv0.y);
            FMA2(acc[6][2], av3.x, bv1.x); FMA2(acc[6][3], av3.x, bv1.y);
            FMA2(acc[7][0], av3.y, bv0.x); FMA2(acc[7][1], av3.y, bv0.y);
            FMA2(acc[7][2], av3.y, bv1.x); FMA2(acc[7][3], av3.y, bv1.y);
        }

        if (kt + 2 < KT) {
            int wb = kt + 2;
            wb = (wb >= 3) ? wb - 3 * ((wb) / 3) : wb;   // (kt+2)%3
            STORE_STAGE(wb);
        }
        __syncthreads();
        buf = (buf == 2) ? 0 : buf + 1;
    }
#undef STORE_STAGE

    // ---------------- epilogue ----------------
    float bias[8];
#pragma unroll
    for (int j = 0; j < 8; j++)
        bias[j] = Bv[(size_t)e * NLD + n0 + tx * 8 + j];

#pragma unroll
    for (int ii = 0; ii < 8; ++ii) {
        int rloc = (ii < 4) ? (ty * 4 + ii) : (64 + ty * 4 + (ii - 4));
        int r = row_base + rloc;
        float c[8];
        UNPACK2F(c[0], c[1], acc[ii][0]);
        UNPACK2F(c[2], c[3], acc[ii][1]);
        UNPACK2F(c[4], c[5], acc[ii][2]);
        UNPACK2F(c[6], c[7], acc[ii][3]);
        if (LAYER1) {
            float* dst = g_h + (size_t)r * NLD + n0 + tx * 8;
            float4 o0, o1;
            o0.x = gelu_exact(c[0] + bias[0]);
            o0.y = gelu_exact(c[1] + bias[1]);
            o0.z = gelu_exact(c[2] + bias[2]);
            o0.w = gelu_exact(c[3] + bias[3]);
            o1.x = gelu_exact(c[4] + bias[4]);
            o1.y = gelu_exact(c[5] + bias[5]);
            o1.z = gelu_exact(c[6] + bias[6]);
            o1.w = gelu_exact(c[7] + bias[7]);
            *(float4*)(dst) = o0;
            *(float4*)(dst + 4) = o1;
        } else {
            float s = g_row_scale[r];
            float* dst = g_y + (size_t)r * NLD + n0 + tx * 8;
            float4 o0, o1;
            o0.x = (c[0] + bias[0]) * s;
            o0.y = (c[1] + bias[1]) * s;
            o0.z = (c[2] + bias[2]) * s;
            o0.w = (c[3] + bias[3]) * s;
            o1.x = (c[4] + bias[4]) * s;
            o1.y = (c[5] + bias[5]) * s;
            o1.z = (c[6] + bias[6]) * s;
            o1.w = (c[7] + bias[7]) * s;
            *(float4*)(dst) = o0;
            *(float4*)(dst + 4) = o1;
        }
    }
}

// ---------------- combine: out[t] = y[row(t,0)] + y[row(t,1)] ----------------
__global__ void combine_kernel(float* __restrict__ out) {
    int t = blockIdx.x;
    int r0 = g_dest_row[2 * t + 0];
    int r1 = g_dest_row[2 * t + 1];
    const float4* y0 = (const float4*)(g_y + (size_t)r0 * DMODEL);
    const float4* y1 = (const float4*)(g_y + (size_t)r1 * DMODEL);
    float4* o = (float4*)(out + (size_t)t * DMODEL);
    int i = threadIdx.x;  // 128 threads, 128 float4s per row
    float4 a = y0[i], b = y1[i];
    float4 r;
    r.x = a.x + b.x; r.y = a.y + b.y; r.z = a.z + b.z; r.w = a.w + b.w;
    o[i] = r;
}

// ---------------- launch ----------------
extern "C" void kernel_launch(void* const* d_in, const int* in_sizes, int n_in,
                              void* d_out, int out_size) {
    const float* x      = (const float*)d_in[0];
    const float* gate_w = (const float*)d_in[1];
    const float* gate_b = (const float*)d_in[2];
    const float* w1     = (const float*)d_in[3];
    const float* b1     = (const float*)d_in[4];
    const float* w2     = (const float*)d_in[5];
    const float* b2     = (const float*)d_in[6];
    float* out = (float*)d_out;

    init_kernel<<<(PAD_CAP + 255) / 256, 256>>>();
    gate_kernel<<<T_TOK / 8, 256>>>(x, gate_w, gate_b);
    offsets_kernel<<<1, 32>>>();
    scatter_kernel<<<NDISP / 256, 256>>>();
    gemm_kernel<DMODEL, HDIM, true><<<dim3(HDIM / 128, MAXTILES), 256>>>(x, w1, b1);
    gemm_kernel<HDIM, DMODEL, false><<<dim3(DMODEL / 128, MAXTILES), 256>>>(nullptr, w2, b2);
    combine_kernel<<<T_TOK, 128>>>(out);
}

// round 9
// speedup vs baseline: 1.2563x; 1.2563x over previous
#include <cuda_runtime.h>
#include <cuda_bf16.h>
#include <math.h>
#include <stdint.h>

// Problem constants (fixed shapes)
#define T_TOK   16384
#define DMODEL  512
#define HDIM    1024
#define NEXP    8
#define NDISP   (T_TOK * 2)              // T * top_k
#define PAD_CAP (NDISP + NEXP * 128)     // per-expert padding to 128-row tiles
#define MAXTILES ((NDISP / 128) + NEXP)  // 264

// ---------------- scratch (device globals; no allocations) ----------------
__device__ float g_h[(size_t)PAD_CAP * HDIM];   // GEMM1 output (post-GELU)
__device__ float g_y[(size_t)PAD_CAP * DMODEL]; // GEMM2 output (pre-scaled)
__device__ float g_zero[DMODEL];                // zero row for padded gathers
__device__ int   g_row_disp[PAD_CAP];           // padded row -> dispatch idx (or -1)
__device__ float g_row_scale[PAD_CAP];          // gate score per padded row
__device__ int   g_dest_row[NDISP];             // dispatch idx -> padded row
__device__ int   g_expert_of[NDISP];
__device__ float g_scale_of[NDISP];
__device__ int   g_count[NEXP];
__device__ int   g_cursor[NEXP];
__device__ int   g_pad_off[NEXP];
__device__ int   g_tile_start[NEXP + 1];

// ---------------- packed f32x2 helpers ----------------
#define PACKDUP(dst, xf)                                               \
    asm("mov.b64 %0, {%1, %1};" : "=l"(dst) : "r"(__float_as_uint(xf)))

#define FMA2(acc, a2, b2)                                              \
    asm("fma.rn.f32x2 %0, %1, %2, %0;" : "+l"(acc) : "l"(a2), "l"(b2))

#define UNPACK2F(xf, yf, src)                                          \
    do {                                                               \
        uint32_t u0_, u1_;                                             \
        asm("mov.b64 {%0, %1}, %2;" : "=r"(u0_), "=r"(u1_) : "l"(src));\
        xf = __uint_as_float(u0_);                                     \
        yf = __uint_as_float(u1_);                                     \
    } while (0)

// ---------------- init ----------------
__global__ void init_kernel() {
    int i = blockIdx.x * blockDim.x + threadIdx.x;
    if (i < PAD_CAP) { g_row_disp[i] = -1; g_row_scale[i] = 0.f; }
    if (i < NEXP)    { g_count[i] = 0; g_cursor[i] = 0; }
}

// ---------------- gating: logits -> top2 -> softmax ----------------
__global__ void gate_kernel(const float* __restrict__ x,
                            const float* __restrict__ gw,
                            const float* __restrict__ gb) {
    int warp = threadIdx.x >> 5, lane = threadIdx.x & 31;
    int t = blockIdx.x * 8 + warp;
    if (t >= T_TOK) return;

    float acc[NEXP];
#pragma unroll
    for (int e = 0; e < NEXP; e++) acc[e] = 0.f;

    const float* xr = x + (size_t)t * DMODEL;
    for (int i = lane; i < DMODEL; i += 32) {
        float xv = xr[i];
        const float4* g4 = (const float4*)(gw + (size_t)i * NEXP);
        float4 a = g4[0], b = g4[1];
        acc[0] += xv * a.x; acc[1] += xv * a.y; acc[2] += xv * a.z; acc[3] += xv * a.w;
        acc[4] += xv * b.x; acc[5] += xv * b.y; acc[6] += xv * b.z; acc[7] += xv * b.w;
    }
#pragma unroll
    for (int e = 0; e < NEXP; e++) {
#pragma unroll
        for (int off = 16; off > 0; off >>= 1)
            acc[e] += __shfl_xor_sync(0xFFFFFFFFu, acc[e], off);
    }

    if (lane == 0) {
        float v0 = -1e30f, v1 = -1e30f; int i0 = 0, i1 = 0;
#pragma unroll
        for (int e = 0; e < NEXP; e++) {
            float v = acc[e] + gb[e];
            if (v > v0) { v1 = v0; i1 = i0; v0 = v; i0 = e; }
            else if (v > v1) { v1 = v; i1 = e; }
        }
        float ed = expf(v1 - v0);
        float inv = 1.f / (1.f + ed);
        g_expert_of[2 * t + 0] = i0; g_scale_of[2 * t + 0] = inv;
        g_expert_of[2 * t + 1] = i1; g_scale_of[2 * t + 1] = ed * inv;
        atomicAdd(&g_count[i0], 1);
        atomicAdd(&g_count[i1], 1);
    }
}

// ---------------- padded offsets ----------------
__global__ void offsets_kernel() {
    if (threadIdx.x == 0) {
        int off = 0, ts = 0;
        for (int e = 0; e < NEXP; e++) {
            g_pad_off[e] = off;
            g_tile_start[e] = ts;
            int tiles = (g_count[e] + 127) >> 7;
            ts += tiles;
            off += tiles * 128;
        }
        g_tile_start[NEXP] = ts;
    }
}

// ---------------- scatter dispatches into padded rows ----------------
__global__ void scatter_kernel() {
    int j = blockIdx.x * blockDim.x + threadIdx.x;
    if (j >= NDISP) return;
    int e = g_expert_of[j];
    int pos = atomicAdd(&g_cursor[e], 1);
    int r = g_pad_off[e] + pos;
    g_row_disp[r] = j;
    g_row_scale[r] = g_scale_of[j];
    g_dest_row[j] = r;
}

__device__ __forceinline__ float gelu_exact(float v) {
    return 0.5f * v * (1.f + erff(v * 0.70710678118654752440f));
}

// ---------------- grouped GEMM: 128x128x8, FMA2, 3-stage ring, 1 sync/kt ----------------
// As: [3][8][128] floats, column-major per kk (A[r][kk] at As[kk][r])
// Bs: [3][8][128] floats, natural row layout (pairs contiguous -> direct u64x2 reads)
template <int KDIM, int NLD, bool LAYER1>
__global__ __launch_bounds__(256, 2) void gemm_kernel(const float* __restrict__ X,
                                                      const float* __restrict__ W,
                                                      const float* __restrict__ Bv) {
    __shared__ __align__(16) float As[3][8][128];
    __shared__ __align__(16) float Bs[3][8][128];
    __shared__ const float* Aptr[128];

    int rt = blockIdx.y;
    if (rt >= g_tile_start[NEXP]) return;
    int e = 0;
    while (e < NEXP - 1 && g_tile_start[e + 1] <= rt) e++;
    int row_base = g_pad_off[e] + (rt - g_tile_start[e]) * 128;
    int n0 = blockIdx.x * 128;

    int tid = threadIdx.x;
    if (tid < 128) {
        if (LAYER1) {
            int j = g_row_disp[row_base + tid];
            Aptr[tid] = (j >= 0) ? (X + (size_t)(j >> 1) * KDIM) : g_zero;
        } else {
            Aptr[tid] = g_h + (size_t)(row_base + tid) * KDIM;
        }
    }
    __syncthreads();

    const float* Wb = W + (size_t)e * KDIM * NLD + n0;

    // loader indices
    const int arow = tid >> 1, ahalf = tid & 1;      // A: row, k-half(4)
    const int brow = tid >> 5, bchunk = tid & 31;    // B: kk row, 16B chunk
    const float* aSrc = Aptr[arow] + ahalf * 4;
    const float* bSrc = Wb + (size_t)brow * NLD + bchunk * 4;

    // compute indices (R1-style column split: cols tx*4 and 64+tx*4)
    const int tx = tid & 15, ty = tid >> 4;

    uint64_t acc[8][4];
#pragma unroll
    for (int i = 0; i < 8; i++)
#pragma unroll
        for (int jp = 0; jp < 4; jp++) acc[i][jp] = 0ull;

    const int KT = KDIM / 8;
    float4 aReg, bReg;

#define STORE_STAGE(sbuf)                                                   \
    do {                                                                    \
        As[sbuf][ahalf * 4 + 0][arow] = aReg.x;                             \
        As[sbuf][ahalf * 4 + 1][arow] = aReg.y;                             \
        As[sbuf][ahalf * 4 + 2][arow] = aReg.z;                             \
        As[sbuf][ahalf * 4 + 3][arow] = aReg.w;                             \
        *(float4*)&Bs[sbuf][brow][bchunk * 4] = bReg;                       \
    } while (0)

    // prologue: fill stages 0 and 1
    aReg = *(const float4*)(aSrc);
    bReg = *(const float4*)(bSrc);
    STORE_STAGE(0);
    if (KT > 1) {
        aReg = *(const float4*)(aSrc + 8);
        bReg = *(const float4*)(bSrc + (size_t)8 * NLD);
        STORE_STAGE(1);
    }
    __syncthreads();

    int buf = 0;
    for (int kt = 0; kt < KT; ++kt) {
        if (kt + 2 < KT) {
            aReg = *(const float4*)(aSrc + (kt + 2) * 8);
            bReg = *(const float4*)(bSrc + (size_t)(kt + 2) * 8 * NLD);
        }

#pragma unroll
        for (int kk = 0; kk < 8; ++kk) {
            // A broadcast rows (conflict-free), dup-packed in regs
            float4 a0 = *(const float4*)&As[buf][kk][ty * 4];
            float4 a1 = *(const float4*)&As[buf][kk][64 + ty * 4];
            // B natural pairs straight from shared (stride-16B, conflict-free)
            ulonglong2 bv0 = *(const ulonglong2*)&Bs[buf][kk][tx * 4];
            ulonglong2 bv1 = *(const ulonglong2*)&Bs[buf][kk][64 + tx * 4];

            uint64_t aa;
            PACKDUP(aa, a0.x);
            FMA2(acc[0][0], aa, bv0.x); FMA2(acc[0][1], aa, bv0.y);
            FMA2(acc[0][2], aa, bv1.x); FMA2(acc[0][3], aa, bv1.y);
            PACKDUP(aa, a0.y);
            FMA2(acc[1][0], aa, bv0.x); FMA2(acc[1][1], aa, bv0.y);
            FMA2(acc[1][2], aa, bv1.x); FMA2(acc[1][3], aa, bv1.y);
            PACKDUP(aa, a0.z);
            FMA2(acc[2][0], aa, bv0.x); FMA2(acc[2][1], aa, bv0.y);
            FMA2(acc[2][2], aa, bv1.x); FMA2(acc[2][3], aa, bv1.y);
            PACKDUP(aa, a0.w);
            FMA2(acc[3][0], aa, bv0.x); FMA2(acc[3][1], aa, bv0.y);
            FMA2(acc[3][2], aa, bv1.x); FMA2(acc[3][3], aa, bv1.y);
            PACKDUP(aa, a1.x);
            FMA2(acc[4][0], aa, bv0.x); FMA2(acc[4][1], aa, bv0.y);
            FMA2(acc[4][2], aa, bv1.x); FMA2(acc[4][3], aa, bv1.y);
            PACKDUP(aa, a1.y);
            FMA2(acc[5][0], aa, bv0.x); FMA2(acc[5][1], aa, bv0.y);
            FMA2(acc[5][2], aa, bv1.x); FMA2(acc[5][3], aa, bv1.y);
            PACKDUP(aa, a1.z);
            FMA2(acc[6][0], aa, bv0.x); FMA2(acc[6][1], aa, bv0.y);
            FMA2(acc[6][2], aa, bv1.x); FMA2(acc[6][3], aa, bv1.y);
            PACKDUP(aa, a1.w);
            FMA2(acc[7][0], aa, bv0.x); FMA2(acc[7][1], aa, bv0.y);
            FMA2(acc[7][2], aa, bv1.x); FMA2(acc[7][3], aa, bv1.y);
        }

        if (kt + 2 < KT) {
            int wb = kt + 2;
            while (wb >= 3) wb -= 3;
            STORE_STAGE(wb);
        }
        __syncthreads();
        buf = (buf == 2) ? 0 : buf + 1;
    }
#undef STORE_STAGE

    // ---------------- epilogue ----------------
    float bias[8];
#pragma unroll
    for (int j = 0; j < 4; j++) {
        bias[j]     = Bv[(size_t)e * NLD + n0 + tx * 4 + j];
        bias[j + 4] = Bv[(size_t)e * NLD + n0 + 64 + tx * 4 + j];
    }
#pragma unroll
    for (int ii = 0; ii < 8; ++ii) {
        int rloc = (ii < 4) ? (ty * 4 + ii) : (64 + ty * 4 + (ii - 4));
        int r = row_base + rloc;
        float c[8];
        UNPACK2F(c[0], c[1], acc[ii][0]);
        UNPACK2F(c[2], c[3], acc[ii][1]);
        UNPACK2F(c[4], c[5], acc[ii][2]);
        UNPACK2F(c[6], c[7], acc[ii][3]);
        if (LAYER1) {
            float* dst = g_h + (size_t)r * NLD + n0;
            float4 o0, o1;
            o0.x = gelu_exact(c[0] + bias[0]);
            o0.y = gelu_exact(c[1] + bias[1]);
            o0.z = gelu_exact(c[2] + bias[2]);
            o0.w = gelu_exact(c[3] + bias[3]);
            o1.x = gelu_exact(c[4] + bias[4]);
            o1.y = gelu_exact(c[5] + bias[5]);
            o1.z = gelu_exact(c[6] + bias[6]);
            o1.w = gelu_exact(c[7] + bias[7]);
            *(float4*)(dst + tx * 4) = o0;
            *(float4*)(dst + 64 + tx * 4) = o1;
        } else {
            float s = g_row_scale[r];
            float* dst = g_y + (size_t)r * NLD + n0;
            float4 o0, o1;
            o0.x = (c[0] + bias[0]) * s;
            o0.y = (c[1] + bias[1]) * s;
            o0.z = (c[2] + bias[2]) * s;
            o0.w = (c[3] + bias[3]) * s;
            o1.x = (c[4] + bias[4]) * s;
            o1.y = (c[5] + bias[5]) * s;
            o1.z = (c[6] + bias[6]) * s;
            o1.w = (c[7] + bias[7]) * s;
            *(float4*)(dst + tx * 4) = o0;
            *(float4*)(dst + 64 + tx * 4) = o1;
        }
    }
}

// ---------------- combine: out[t] = y[row(t,0)] + y[row(t,1)] ----------------
__global__ void combine_kernel(float* __restrict__ out) {
    int t = blockIdx.x;
    int r0 = g_dest_row[2 * t + 0];
    int r1 = g_dest_row[2 * t + 1];
    const float4* y0 = (const float4*)(g_y + (size_t)r0 * DMODEL);
    const float4* y1 = (const float4*)(g_y + (size_t)r1 * DMODEL);
    float4* o = (float4*)(out + (size_t)t * DMODEL);
    int i = threadIdx.x;  // 128 threads, 128 float4s per row
    float4 a = y0[i], b = y1[i];
    float4 r;
    r.x = a.x + b.x; r.y = a.y + b.y; r.z = a.z + b.z; r.w = a.w + b.w;
    o[i] = r;
}

// ---------------- launch ----------------
extern "C" void kernel_launch(void* const* d_in, const int* in_sizes, int n_in,
                              void* d_out, int out_size) {
    const float* x      = (const float*)d_in[0];
    const float* gate_w = (const float*)d_in[1];
    const float* gate_b = (const float*)d_in[2];
    const float* w1     = (const float*)d_in[3];
    const float* b1     = (const float*)d_in[4];
    const float* w2     = (const float*)d_in[5];
    const float* b2     = (const float*)d_in[6];
    float* out = (float*)d_out;

    init_kernel<<<(PAD_CAP + 255) / 256, 256>>>();
    gate_kernel<<<T_TOK / 8, 256>>>(x, gate_w, gate_b);
    offsets_kernel<<<1, 32>>>();
    scatter_kernel<<<NDISP / 256, 256>>>();
    gemm_kernel<DMODEL, HDIM, true><<<dim3(HDIM / 128, MAXTILES), 256>>>(x, w1, b1);
    gemm_kernel<HDIM, DMODEL, false><<<dim3(DMODEL / 128, MAXTILES), 256>>>(nullptr, w2, b2);
    combine_kernel<<<T_TOK, 128>>>(out);
}